// round 13
// baseline (speedup 1.0000x reference)
#include <cuda_runtime.h>

#define EMB 64
#define NSEG_MAX 4097
#define THREADS 256

__device__ float g_wvo[EMB];     // w_value @ w_out
__device__ float g_c;            // b_value.w_out + b_out
__device__ float g_b0;           // b_out[0]
__device__ int   g_starts[NSEG_MAX];

// Kernel 1: segment-bounds scan (int4-vectorized, shfl for neighbor) +
// fused-head precompute in block 0.
__global__ __launch_bounds__(THREADS)
void bounds_kernel(const int*   __restrict__ ids,
                   const float* __restrict__ w_value,
                   const float* __restrict__ b_value,
                   const float* __restrict__ w_out,
                   const float* __restrict__ b_out,
                   int Btot, int Nimg) {
    const int tid = threadIdx.x;
    const int t   = blockIdx.x * THREADS + tid;   // vector index (4 ids each)
    const int i0  = t * 4;

    if (blockIdx.x == 0 && tid < EMB) {
        float s = 0.f;
#pragma unroll
        for (int h = 0; h < EMB; ++h)
            s = fmaf(__ldg(w_value + tid * EMB + h), __ldg(w_out + h), s);
        g_wvo[tid] = s;
        if (tid == 0) {
            float c = 0.f;
#pragma unroll
            for (int h = 0; h < EMB; ++h) c = fmaf(__ldg(b_value + h), __ldg(w_out + h), c);
            g_c  = c + __ldg(b_out);
            g_b0 = __ldg(b_out);
        }
    }

    if (i0 < Btot) {
        const int4 cur = __ldg(reinterpret_cast<const int4*>(ids) + t);
        int prev = __shfl_up_sync(0xffffffffu, cur.w, 1);
        if ((tid & 31) == 0 && i0 > 0) prev = __ldg(ids + i0 - 1);

        if (i0 == 0) {
            for (int j = 0; j <= cur.x; ++j) g_starts[j] = 0;
        } else {
            for (int j = prev + 1; j <= cur.x; ++j) g_starts[j] = i0;
        }
        for (int j = cur.x + 1; j <= cur.y; ++j) g_starts[j] = i0 + 1;
        for (int j = cur.y + 1; j <= cur.z; ++j) g_starts[j] = i0 + 2;
        for (int j = cur.z + 1; j <= cur.w; ++j) g_starts[j] = i0 + 3;

        if (i0 + 4 >= Btot) {
            for (int j = cur.w + 1; j <= Nimg; ++j) g_starts[j] = Btot;
        }
    }
}

// Kernel 2: one CTA (2 warps) per segment; each warp streams a contiguous
// half. 4-way unroll (8 rows / 4 front-batched LDG.128 per iter) keeps regs
// ~44 so ~20+ CTAs (40+ warps) fit per SM. 16 lanes/row; score partial
// shfl-reduced per row; exp replicated; value partials reduced per warp,
// combined via a 2-entry smem exchange.
__global__ __launch_bounds__(64, 20)
void pool_kernel(const float* __restrict__ emb,
                 const float* __restrict__ w_attn,
                 float* __restrict__ out,
                 int Btot, int Nimg) {
    const int n    = blockIdx.x;            // segment id
    const int tid  = threadIdx.x;
    const int wid  = tid >> 5;              // warp 0/1
    const int lane = tid & 31;
    const int grp  = lane & 15;             // column slice [4*grp, 4*grp+4)
    const int half = lane >> 4;             // row slot 0/1

    const float4 wa = reinterpret_cast<const float4*>(w_attn)[grp];
    const float4 wv = reinterpret_cast<const float4*>(g_wvo)[grp];

    const int start = g_starts[n];
    const int end   = g_starts[n + 1];
    const int cnt   = end - start;

    // contiguous split: warp0 gets first h rows (h multiple of 8), warp1 rest
    const int h  = ((cnt >> 1) + 7) & ~7;
    const int ws = start + (wid ? h : 0);
    const int we = wid ? end : min(start + h, end);
    const int wcnt = we - ws;               // may be <= 0 for warp1

    float se0 = 0.f, sev0 = 0.f, se1 = 0.f, sev1 = 0.f;

    const float4* const pbase = reinterpret_cast<const float4*>(emb) + grp;
    const int mid = ws + (wcnt > 0 ? (wcnt & ~7) : 0);

    // ---- main loop: 4 independent LDG.128 (evict-first) front-batched ----
    for (int base = ws; base < mid; base += 8) {
        float4 e[4];
#pragma unroll
        for (int u = 0; u < 4; ++u)
            e[u] = __ldcs(pbase + ((size_t)(base + u * 2 + half) << 4));
#pragma unroll
        for (int u = 0; u < 4; ++u) {
            float sp = e[u].x * wa.x + e[u].y * wa.y + e[u].z * wa.z + e[u].w * wa.w;
            float vp = e[u].x * wv.x + e[u].y * wv.y + e[u].z * wv.z + e[u].w * wv.w;
#pragma unroll
            for (int o = 8; o; o >>= 1) sp += __shfl_xor_sync(0xffffffffu, sp, o);
            const float ex = __expf(sp);            // replicated on 16-lane group
            if (u & 1) { se1 += ex; sev1 = fmaf(ex, vp, sev1); }
            else       { se0 += ex; sev0 = fmaf(ex, vp, sev0); }
        }
    }

    // ---- masked tail (up to 7 rows) ----
    if (mid < we) {
#pragma unroll
        for (int u = 0; u < 4; ++u) {
            const int row = mid + u * 2 + half;
            const bool v = row < we;
            float4 e = make_float4(0.f, 0.f, 0.f, 0.f);
            if (v) e = __ldcs(pbase + ((size_t)row << 4));
            float sp = e.x * wa.x + e.y * wa.y + e.z * wa.z + e.w * wa.w;
            float vp = e.x * wv.x + e.y * wv.y + e.z * wv.z + e.w * wv.w;
#pragma unroll
            for (int o = 8; o; o >>= 1) sp += __shfl_xor_sync(0xffffffffu, sp, o);
            const float ex = v ? __expf(sp) : 0.f;
            se0 += ex; sev0 = fmaf(ex, vp, sev0);
        }
    }

    // ---- per-warp reduction ----
    float se  = se0 + se1;                       // replicated within 16-group
    float sev = sev0 + sev1;
    se += __shfl_xor_sync(0xffffffffu, se, 16);
#pragma unroll
    for (int o = 16; o; o >>= 1) sev += __shfl_xor_sync(0xffffffffu, sev, o);

    // ---- combine the two warps (cheap: 2 entries + 1 barrier) ----
    __shared__ float s_se[2], s_sev[2], s_r;
    if (lane == 0) { s_se[wid] = se; s_sev[wid] = sev; }
    __syncthreads();
    if (tid == 0) {
        const float SE  = s_se[0] + s_se[1];
        const float SEV = s_sev[0] + s_sev[1];
        const float r = (cnt == 0) ? g_b0 : (SEV / SE + g_c);
        out[Btot + n]        = r;          // r_images
        out[Btot + Nimg + n] = (float)n;   // unique_ids
        s_r = r;
    }
    __syncthreads();

    const float r = s_r;
    for (int i = start + tid; i < end; i += 64) out[i] = r;   // r_reflections
}

extern "C" void kernel_launch(void* const* d_in, const int* in_sizes, int n_in,
                              void* d_out, int out_size) {
    const float* emb     = (const float*)d_in[0];
    const int*   ids     = (const int*)  d_in[1];
    const float* w_attn  = (const float*)d_in[2];
    // d_in[3] = b_attn: cancels under softmax shift invariance
    const float* w_value = (const float*)d_in[4];
    const float* b_value = (const float*)d_in[5];
    const float* w_out   = (const float*)d_in[6];
    const float* b_out   = (const float*)d_in[7];
    float* out = (float*)d_out;

    const int Btot = in_sizes[0] / EMB;          // 1048576 (divisible by 4)
    const int Nimg = (out_size - Btot) / 2;      // 4096

    const int nvec = (Btot + 3) / 4;             // int4 elements
    bounds_kernel<<<(nvec + THREADS - 1) / THREADS, THREADS>>>(
        ids, w_value, b_value, w_out, b_out, Btot, Nimg);
    pool_kernel<<<Nimg, 64>>>(emb, w_attn, out, Btot, Nimg);
}

// round 14
// speedup vs baseline: 1.0069x; 1.0069x over previous
#include <cuda_runtime.h>

#define EMB 64
#define NSEG_MAX 4097
#define THREADS 256

__device__ float g_wvo[EMB];     // w_value @ w_out
__device__ float g_c;            // b_value.w_out + b_out
__device__ float g_b0;           // b_out[0]
__device__ int   g_starts[NSEG_MAX];

// Kernel 1: segment-bounds scan (int4-vectorized, shfl for neighbor) +
// fused-head precompute in block 0.
__global__ __launch_bounds__(THREADS)
void bounds_kernel(const int*   __restrict__ ids,
                   const float* __restrict__ w_value,
                   const float* __restrict__ b_value,
                   const float* __restrict__ w_out,
                   const float* __restrict__ b_out,
                   int Btot, int Nimg) {
    const int tid = threadIdx.x;
    const int t   = blockIdx.x * THREADS + tid;   // vector index (4 ids each)
    const int i0  = t * 4;

    if (blockIdx.x == 0 && tid < EMB) {
        float s = 0.f;
#pragma unroll
        for (int h = 0; h < EMB; ++h)
            s = fmaf(__ldg(w_value + tid * EMB + h), __ldg(w_out + h), s);
        g_wvo[tid] = s;
        if (tid == 0) {
            float c = 0.f;
#pragma unroll
            for (int h = 0; h < EMB; ++h) c = fmaf(__ldg(b_value + h), __ldg(w_out + h), c);
            g_c  = c + __ldg(b_out);
            g_b0 = __ldg(b_out);
        }
    }

    if (i0 < Btot) {
        const int4 cur = __ldg(reinterpret_cast<const int4*>(ids) + t);
        int prev = __shfl_up_sync(0xffffffffu, cur.w, 1);
        if ((tid & 31) == 0 && i0 > 0) prev = __ldg(ids + i0 - 1);

        if (i0 == 0) {
            for (int j = 0; j <= cur.x; ++j) g_starts[j] = 0;
        } else {
            for (int j = prev + 1; j <= cur.x; ++j) g_starts[j] = i0;
        }
        for (int j = cur.x + 1; j <= cur.y; ++j) g_starts[j] = i0 + 1;
        for (int j = cur.y + 1; j <= cur.z; ++j) g_starts[j] = i0 + 2;
        for (int j = cur.z + 1; j <= cur.w; ++j) g_starts[j] = i0 + 3;

        if (i0 + 4 >= Btot) {
            for (int j = cur.w + 1; j <= Nimg; ++j) g_starts[j] = Btot;
        }
    }
}

// Kernel 2: one warp = one CTA = one segment. 8 LANES PER ROW: lane covers
// row chunks ci and ci+8 (two float4s). Per 16-row iteration: 8 front-batched
// LDG.128 (4 full lines each — perfectly coalesced), score reduced with a
// 3-level shfl over the 8-lane group, exp replicated x8, value partials
// reduced once per segment. No smem, no barriers.
__global__ __launch_bounds__(32)
void pool_kernel(const float* __restrict__ emb,
                 const float* __restrict__ w_attn,
                 float* __restrict__ out,
                 int Btot, int Nimg) {
    const int n    = blockIdx.x;            // segment id
    const int lane = threadIdx.x;
    const int rs   = lane >> 3;             // row slot 0..3
    const int ci   = lane & 7;              // chunk index 0..7

    const float4 wa0 = reinterpret_cast<const float4*>(w_attn)[ci];
    const float4 wa1 = reinterpret_cast<const float4*>(w_attn)[ci + 8];
    const float4 wv0 = reinterpret_cast<const float4*>(g_wvo)[ci];
    const float4 wv1 = reinterpret_cast<const float4*>(g_wvo)[ci + 8];

    const int start = g_starts[n];
    const int end   = g_starts[n + 1];
    const int cnt   = end - start;

    float se0 = 0.f, sev0 = 0.f, se1 = 0.f, sev1 = 0.f;
    float se2 = 0.f, sev2 = 0.f, se3 = 0.f, sev3 = 0.f;

    const float4* const pbase = reinterpret_cast<const float4*>(emb) + ci;
    const int mid = start + (cnt & ~15);    // 16 rows per iteration

    // ---- main loop: 8 independent LDG.128 (evict-first) front-batched ----
    for (int base = start; base < mid; base += 16) {
        float4 e[8];
#pragma unroll
        for (int u = 0; u < 4; ++u) {
            const size_t ro = (size_t)(base + u * 4 + rs) << 4;
            e[2 * u]     = __ldcs(pbase + ro);
            e[2 * u + 1] = __ldcs(pbase + ro + 8);
        }
#pragma unroll
        for (int u = 0; u < 4; ++u) {
            const float4 a = e[2 * u], b = e[2 * u + 1];
            float sp = a.x * wa0.x + a.y * wa0.y + a.z * wa0.z + a.w * wa0.w
                     + b.x * wa1.x + b.y * wa1.y + b.z * wa1.z + b.w * wa1.w;
            float vp = a.x * wv0.x + a.y * wv0.y + a.z * wv0.z + a.w * wv0.w
                     + b.x * wv1.x + b.y * wv1.y + b.z * wv1.z + b.w * wv1.w;
#pragma unroll
            for (int o = 4; o; o >>= 1) sp += __shfl_xor_sync(0xffffffffu, sp, o);
            const float ex = __expf(sp);            // replicated on the 8-lane group
            if      (u == 0) { se0 += ex; sev0 = fmaf(ex, vp, sev0); }
            else if (u == 1) { se1 += ex; sev1 = fmaf(ex, vp, sev1); }
            else if (u == 2) { se2 += ex; sev2 = fmaf(ex, vp, sev2); }
            else             { se3 += ex; sev3 = fmaf(ex, vp, sev3); }
        }
    }

    // ---- masked tail (up to 15 rows) ----
    if (mid < end) {
#pragma unroll
        for (int u = 0; u < 4; ++u) {
            const int row = mid + u * 4 + rs;
            const bool v = row < end;
            float4 a = make_float4(0.f, 0.f, 0.f, 0.f);
            float4 b = make_float4(0.f, 0.f, 0.f, 0.f);
            if (v) {
                const size_t ro = (size_t)row << 4;
                a = __ldcs(pbase + ro);
                b = __ldcs(pbase + ro + 8);
            }
            float sp = a.x * wa0.x + a.y * wa0.y + a.z * wa0.z + a.w * wa0.w
                     + b.x * wa1.x + b.y * wa1.y + b.z * wa1.z + b.w * wa1.w;
            float vp = a.x * wv0.x + a.y * wv0.y + a.z * wv0.z + a.w * wv0.w
                     + b.x * wv1.x + b.y * wv1.y + b.z * wv1.z + b.w * wv1.w;
#pragma unroll
            for (int o = 4; o; o >>= 1) sp += __shfl_xor_sync(0xffffffffu, sp, o);
            const float ex = v ? __expf(sp) : 0.f;
            se0 += ex; sev0 = fmaf(ex, vp, sev0);
        }
    }

    // ---- once-per-segment reduction (intra-warp only) ----
    float se  = (se0 + se1) + (se2 + se3);       // replicated within 8-lane groups
    float sev = (sev0 + sev1) + (sev2 + sev3);
    se += __shfl_xor_sync(0xffffffffu, se, 8);
    se += __shfl_xor_sync(0xffffffffu, se, 16);
#pragma unroll
    for (int o = 16; o; o >>= 1) sev += __shfl_xor_sync(0xffffffffu, sev, o);

    const float r = (cnt == 0) ? g_b0 : (sev / se + g_c);   // replicated

    if (lane == 0) {
        out[Btot + n]        = r;          // r_images
        out[Btot + Nimg + n] = (float)n;   // unique_ids
    }
    for (int i = start + lane; i < end; i += 32) out[i] = r;   // r_reflections
}

extern "C" void kernel_launch(void* const* d_in, const int* in_sizes, int n_in,
                              void* d_out, int out_size) {
    const float* emb     = (const float*)d_in[0];
    const int*   ids     = (const int*)  d_in[1];
    const float* w_attn  = (const float*)d_in[2];
    // d_in[3] = b_attn: cancels under softmax shift invariance
    const float* w_value = (const float*)d_in[4];
    const float* b_value = (const float*)d_in[5];
    const float* w_out   = (const float*)d_in[6];
    const float* b_out   = (const float*)d_in[7];
    float* out = (float*)d_out;

    const int Btot = in_sizes[0] / EMB;          // 1048576 (divisible by 4)
    const int Nimg = (out_size - Btot) / 2;      // 4096

    const int nvec = (Btot + 3) / 4;             // int4 elements
    bounds_kernel<<<(nvec + THREADS - 1) / THREADS, THREADS>>>(
        ids, w_value, b_value, w_out, b_out, Btot, Nimg);
    pool_kernel<<<Nimg, 32>>>(emb, w_attn, out, Btot, Nimg);
}

// round 15
// speedup vs baseline: 1.0098x; 1.0029x over previous
#include <cuda_runtime.h>

#define EMB 64
#define NSEG_MAX 4097
#define THREADS 256

typedef unsigned long long ull;

__device__ float g_wvo[EMB];     // w_value @ w_out
__device__ float g_c;            // b_value.w_out + b_out
__device__ float g_b0;           // b_out[0]
__device__ int   g_starts[NSEG_MAX];

// ---- packed f32x2 helpers (Blackwell sm_103a) ----
__device__ __forceinline__ ull pk(float lo, float hi) {
    ull r;
    asm("mov.b64 %0, {%1, %2};" : "=l"(r) : "f"(lo), "f"(hi));
    return r;
}
__device__ __forceinline__ ull ffma2(ull a, ull b, ull c) {
    ull d;
    asm("fma.rn.f32x2 %0, %1, %2, %3;" : "=l"(d) : "l"(a), "l"(b), "l"(c));
    return d;
}
__device__ __forceinline__ float2 unpk(ull v) {
    float2 f;
    asm("mov.b64 {%0, %1}, %2;" : "=f"(f.x), "=f"(f.y) : "l"(v));
    return f;
}

// Kernel 1: segment-bounds scan (int4-vectorized, shfl for neighbor) +
// fused-head precompute in block 0.
__global__ __launch_bounds__(THREADS)
void bounds_kernel(const int*   __restrict__ ids,
                   const float* __restrict__ w_value,
                   const float* __restrict__ b_value,
                   const float* __restrict__ w_out,
                   const float* __restrict__ b_out,
                   int Btot, int Nimg) {
    const int tid = threadIdx.x;
    const int t   = blockIdx.x * THREADS + tid;   // vector index (4 ids each)
    const int i0  = t * 4;

    if (blockIdx.x == 0 && tid < EMB) {
        float s = 0.f;
#pragma unroll
        for (int h = 0; h < EMB; ++h)
            s = fmaf(__ldg(w_value + tid * EMB + h), __ldg(w_out + h), s);
        g_wvo[tid] = s;
        if (tid == 0) {
            float c = 0.f;
#pragma unroll
            for (int h = 0; h < EMB; ++h) c = fmaf(__ldg(b_value + h), __ldg(w_out + h), c);
            g_c  = c + __ldg(b_out);
            g_b0 = __ldg(b_out);
        }
    }

    if (i0 < Btot) {
        const int4 cur = __ldg(reinterpret_cast<const int4*>(ids) + t);
        int prev = __shfl_up_sync(0xffffffffu, cur.w, 1);
        if ((tid & 31) == 0 && i0 > 0) prev = __ldg(ids + i0 - 1);

        if (i0 == 0) {
            for (int j = 0; j <= cur.x; ++j) g_starts[j] = 0;
        } else {
            for (int j = prev + 1; j <= cur.x; ++j) g_starts[j] = i0;
        }
        for (int j = cur.x + 1; j <= cur.y; ++j) g_starts[j] = i0 + 1;
        for (int j = cur.y + 1; j <= cur.z; ++j) g_starts[j] = i0 + 2;
        for (int j = cur.z + 1; j <= cur.w; ++j) g_starts[j] = i0 + 3;

        if (i0 + 4 >= Btot) {
            for (int j = cur.w + 1; j <= Nimg; ++j) g_starts[j] = Btot;
        }
    }
}

// Kernel 2: one warp = one CTA = one segment. 8 lanes/row (lane covers row
// chunks ci and ci+8). Dot products via packed fma.rn.f32x2: 8 FFMA2 per
// row-step instead of 16 FFMA, packs shared between score and value chains.
// Score reduced with 3-level shfl over the 8-lane group; exp replicated x8;
// value partials reduced once per segment. No smem, no barriers.
__global__ __launch_bounds__(32)
void pool_kernel(const float* __restrict__ emb,
                 const float* __restrict__ w_attn,
                 float* __restrict__ out,
                 int Btot, int Nimg) {
    const int n    = blockIdx.x;            // segment id
    const int lane = threadIdx.x;
    const int rs   = lane >> 3;             // row slot 0..3
    const int ci   = lane & 7;              // chunk index 0..7

    const float4 wa0 = reinterpret_cast<const float4*>(w_attn)[ci];
    const float4 wa1 = reinterpret_cast<const float4*>(w_attn)[ci + 8];
    const float4 wv0 = reinterpret_cast<const float4*>(g_wvo)[ci];
    const float4 wv1 = reinterpret_cast<const float4*>(g_wvo)[ci + 8];

    // packed weights (once per warp)
    const ull waA = pk(wa0.x, wa0.y), waB = pk(wa0.z, wa0.w);
    const ull waC = pk(wa1.x, wa1.y), waD = pk(wa1.z, wa1.w);
    const ull wvA = pk(wv0.x, wv0.y), wvB = pk(wv0.z, wv0.w);
    const ull wvC = pk(wv1.x, wv1.y), wvD = pk(wv1.z, wv1.w);

    const int start = g_starts[n];
    const int end   = g_starts[n + 1];
    const int cnt   = end - start;

    float se0 = 0.f, sev0 = 0.f, se1 = 0.f, sev1 = 0.f;
    float se2 = 0.f, sev2 = 0.f, se3 = 0.f, sev3 = 0.f;

    const float4* const pbase = reinterpret_cast<const float4*>(emb) + ci;
    const int mid = start + (cnt & ~15);    // 16 rows per iteration

    // ---- main loop: 8 independent LDG.128 (evict-first) front-batched ----
    for (int base = start; base < mid; base += 16) {
        float4 e[8];
#pragma unroll
        for (int u = 0; u < 4; ++u) {
            const size_t ro = (size_t)(base + u * 4 + rs) << 4;
            e[2 * u]     = __ldcs(pbase + ro);
            e[2 * u + 1] = __ldcs(pbase + ro + 8);
        }
#pragma unroll
        for (int u = 0; u < 4; ++u) {
            const float4 a = e[2 * u], b = e[2 * u + 1];
            const ull pa = pk(a.x, a.y), pb = pk(a.z, a.w);
            const ull pc = pk(b.x, b.y), pd = pk(b.z, b.w);
            const ull s2 = ffma2(pa, waA, ffma2(pb, waB, ffma2(pc, waC, ffma2(pd, waD, 0ULL))));
            const ull v2 = ffma2(pa, wvA, ffma2(pb, wvB, ffma2(pc, wvC, ffma2(pd, wvD, 0ULL))));
            const float2 sf = unpk(s2);
            const float2 vf = unpk(v2);
            float sp = sf.x + sf.y;
            const float vp = vf.x + vf.y;
#pragma unroll
            for (int o = 4; o; o >>= 1) sp += __shfl_xor_sync(0xffffffffu, sp, o);
            const float ex = __expf(sp);            // replicated on the 8-lane group
            if      (u == 0) { se0 += ex; sev0 = fmaf(ex, vp, sev0); }
            else if (u == 1) { se1 += ex; sev1 = fmaf(ex, vp, sev1); }
            else if (u == 2) { se2 += ex; sev2 = fmaf(ex, vp, sev2); }
            else             { se3 += ex; sev3 = fmaf(ex, vp, sev3); }
        }
    }

    // ---- masked tail (up to 15 rows) ----
    if (mid < end) {
#pragma unroll
        for (int u = 0; u < 4; ++u) {
            const int row = mid + u * 4 + rs;
            const bool v = row < end;
            float4 a = make_float4(0.f, 0.f, 0.f, 0.f);
            float4 b = make_float4(0.f, 0.f, 0.f, 0.f);
            if (v) {
                const size_t ro = (size_t)row << 4;
                a = __ldcs(pbase + ro);
                b = __ldcs(pbase + ro + 8);
            }
            const ull pa = pk(a.x, a.y), pb = pk(a.z, a.w);
            const ull pc = pk(b.x, b.y), pd = pk(b.z, b.w);
            const ull s2 = ffma2(pa, waA, ffma2(pb, waB, ffma2(pc, waC, ffma2(pd, waD, 0ULL))));
            const ull v2 = ffma2(pa, wvA, ffma2(pb, wvB, ffma2(pc, wvC, ffma2(pd, wvD, 0ULL))));
            const float2 sf = unpk(s2);
            const float2 vf = unpk(v2);
            float sp = sf.x + sf.y;
            const float vp = vf.x + vf.y;
#pragma unroll
            for (int o = 4; o; o >>= 1) sp += __shfl_xor_sync(0xffffffffu, sp, o);
            const float ex = v ? __expf(sp) : 0.f;
            se0 += ex; sev0 = fmaf(ex, vp, sev0);
        }
    }

    // ---- once-per-segment reduction (intra-warp only) ----
    float se  = (se0 + se1) + (se2 + se3);       // replicated within 8-lane groups
    float sev = (sev0 + sev1) + (sev2 + sev3);
    se += __shfl_xor_sync(0xffffffffu, se, 8);
    se += __shfl_xor_sync(0xffffffffu, se, 16);
#pragma unroll
    for (int o = 16; o; o >>= 1) sev += __shfl_xor_sync(0xffffffffu, sev, o);

    const float r = (cnt == 0) ? g_b0 : (sev / se + g_c);   // replicated

    if (lane == 0) {
        out[Btot + n]        = r;          // r_images
        out[Btot + Nimg + n] = (float)n;   // unique_ids
    }
    for (int i = start + lane; i < end; i += 32) out[i] = r;   // r_reflections
}

extern "C" void kernel_launch(void* const* d_in, const int* in_sizes, int n_in,
                              void* d_out, int out_size) {
    const float* emb     = (const float*)d_in[0];
    const int*   ids     = (const int*)  d_in[1];
    const float* w_attn  = (const float*)d_in[2];
    // d_in[3] = b_attn: cancels under softmax shift invariance
    const float* w_value = (const float*)d_in[4];
    const float* b_value = (const float*)d_in[5];
    const float* w_out   = (const float*)d_in[6];
    const float* b_out   = (const float*)d_in[7];
    float* out = (float*)d_out;

    const int Btot = in_sizes[0] / EMB;          // 1048576 (divisible by 4)
    const int Nimg = (out_size - Btot) / 2;      // 4096

    const int nvec = (Btot + 3) / 4;             // int4 elements
    bounds_kernel<<<(nvec + THREADS - 1) / THREADS, THREADS>>>(
        ids, w_value, b_value, w_out, b_out, Btot, Nimg);
    pool_kernel<<<Nimg, 32>>>(emb, w_attn, out, Btot, Nimg);
}